// round 5
// baseline (speedup 1.0000x reference)
#include <cuda_runtime.h>
#include <math.h>

#define B_  2
#define T_  2048
#define E_  2048
#define H_  16
#define KVH_ 8
#define D_  128
#define ROWS (B_ * T_)          // 4096

// ---------------- scratch (device globals; no allocation allowed) ----------
__device__ float g_q[(size_t)ROWS * H_ * D_];     // 32 MB
__device__ float g_k[(size_t)ROWS * KVH_ * D_];   // 16 MB
__device__ float g_v[(size_t)ROWS * KVH_ * D_];   // 16 MB
__device__ float g_ctx[(size_t)ROWS * H_ * D_];   // 32 MB
__device__ float g_invf[64];
__device__ float g_cos[T_ * 64];
__device__ float g_sin[T_ * 64];

// ---------------- SGEMM: C[M,N] = A[M,K] @ B[K,N], all row-major, fp32 -----
// BM=BN=128, BK=16, 256 threads, 8x8 per-thread tile. M%128==0, N%128==0, K%16==0.
__global__ __launch_bounds__(256, 2)
void sgemm128(const float* __restrict__ A, const float* __restrict__ Bm,
              float* __restrict__ C, int M, int N, int K)
{
    __shared__ __align__(16) float As[16][132];   // transposed A tile (pad 132)
    __shared__ __align__(16) float Bs[16][128];

    const int tid = threadIdx.x;
    const int bx = blockIdx.x, by = blockIdx.y;
    const int tm = tid >> 4;        // 0..15
    const int tn = tid & 15;        // 0..15

    const float* Ab = A + (size_t)by * 128 * K;
    const float* Bb = Bm + (size_t)bx * 128;

    const int a_r = tid >> 2;          // 0..63
    const int a_k = (tid & 3) << 2;    // 0,4,8,12
    const int b_r = tid >> 5;          // 0..7
    const int b_c = (tid & 31) << 2;   // 0..124

    float acc[8][8];
#pragma unroll
    for (int i = 0; i < 8; i++)
#pragma unroll
        for (int j = 0; j < 8; j++) acc[i][j] = 0.0f;

    for (int k0 = 0; k0 < K; k0 += 16) {
        float4 av0 = *(const float4*)(Ab + (size_t)a_r * K + k0 + a_k);
        float4 av1 = *(const float4*)(Ab + (size_t)(a_r + 64) * K + k0 + a_k);
        float4 bv0 = *(const float4*)(Bb + (size_t)(k0 + b_r) * N + b_c);
        float4 bv1 = *(const float4*)(Bb + (size_t)(k0 + b_r + 8) * N + b_c);

        __syncthreads();     // previous iteration's reads complete
        As[a_k + 0][a_r] = av0.x;  As[a_k + 1][a_r] = av0.y;
        As[a_k + 2][a_r] = av0.z;  As[a_k + 3][a_r] = av0.w;
        As[a_k + 0][a_r + 64] = av1.x;  As[a_k + 1][a_r + 64] = av1.y;
        As[a_k + 2][a_r + 64] = av1.z;  As[a_k + 3][a_r + 64] = av1.w;
        *(float4*)&Bs[b_r][b_c]     = bv0;
        *(float4*)&Bs[b_r + 8][b_c] = bv1;
        __syncthreads();

#pragma unroll
        for (int kk = 0; kk < 16; kk++) {
            float rm[8], rn[8];
            *(float4*)(rm)     = *(const float4*)&As[kk][tm * 8];
            *(float4*)(rm + 4) = *(const float4*)&As[kk][tm * 8 + 4];
            *(float4*)(rn)     = *(const float4*)&Bs[kk][tn * 8];
            *(float4*)(rn + 4) = *(const float4*)&Bs[kk][tn * 8 + 4];
#pragma unroll
            for (int i = 0; i < 8; i++)
#pragma unroll
                for (int j = 0; j < 8; j++)
                    acc[i][j] += rm[i] * rn[j];
        }
    }

    float* Cb = C + (size_t)(by * 128 + tm * 8) * N + bx * 128 + tn * 8;
#pragma unroll
    for (int i = 0; i < 8; i++) {
        *(float4*)(Cb + (size_t)i * N)     = make_float4(acc[i][0], acc[i][1], acc[i][2], acc[i][3]);
        *(float4*)(Cb + (size_t)i * N + 4) = make_float4(acc[i][4], acc[i][5], acc[i][6], acc[i][7]);
    }
}

// ---------------- RoPE ----------------------------------------------------
__global__ void rope_init_kernel()
{
    int j = threadIdx.x;
    if (j < 64)
        g_invf[j] = (float)pow(10000.0, -(double)j / 64.0);
}

__global__ void rope_table_kernel()
{
    int t = blockIdx.x;        // 0..2047
    int j = threadIdx.x;       // 0..63
    float f = (float)t * g_invf[j];   // fp32 product, matching reference
    float s, c;
    sincosf(f, &s, &c);
    g_cos[t * 64 + j] = c;
    g_sin[t * 64 + j] = s;
}

// a: (ROWS, nh*128); rotate pairs in place
__global__ void rope_apply_kernel(float* __restrict__ a, int nh)
{
    int pidx = blockIdx.x * blockDim.x + threadIdx.x;
    int j    = pidx & 63;
    int head = (pidx >> 6) % nh;
    int row  = pidx / (nh * 64);
    int t    = row & (T_ - 1);

    size_t off = (size_t)row * nh * 128 + head * 128 + 2 * j;
    float2 xv = *(float2*)(a + off);
    float c = g_cos[t * 64 + j];
    float s = g_sin[t * 64 + j];
    float2 o;
    o.x = xv.x * c - xv.y * s;
    o.y = xv.x * s + xv.y * c;
    *(float2*)(a + off) = o;
}

// ---------------- Flash attention (fp32 SIMT) ------------------------------
// grid (32 qtiles, 32 bh), 256 threads. BQ=64, BK=64, D=128.
// smem: Qs[64][132], KT[128][68] (transposed K), Vs[64][132], Ss[64][68]
#define FL_SMEM ((64 * 132 + 128 * 68 + 64 * 132 + 64 * 68) * 4)

__global__ __launch_bounds__(256, 1)
void flash_kernel(const float* __restrict__ Q, const float* __restrict__ K,
                  const float* __restrict__ V, float* __restrict__ ctx)
{
    extern __shared__ __align__(16) float sm[];
    float* Qs = sm;                       // 64*132
    float* KT = sm + 64 * 132;            // 128*68
    float* Vs = KT + 128 * 68;            // 64*132
    float* Ss = Vs + 64 * 132;            // 64*68

    const int qt = gridDim.x - 1 - blockIdx.x;   // heavy tiles first
    const int bh = blockIdx.y;
    const int b = bh >> 4, h = bh & 15;
    const int kvh = h >> 1;
    const int tid = threadIdx.x;
    const int ty = tid >> 4, tx = tid & 15;

    const float* Qg = Q + (size_t)b * T_ * 2048 + (size_t)h * 128;
    const float* Kg = K + (size_t)b * T_ * 1024 + (size_t)kvh * 128;
    const float* Vg = V + (size_t)b * T_ * 1024 + (size_t)kvh * 128;

    // load Q tile
    {
        const int r = tid & 63, d0 = (tid >> 6) * 32;
#pragma unroll
        for (int i = 0; i < 8; i++) {
            float4 tv = *(const float4*)(Qg + (size_t)(qt * 64 + r) * 2048 + d0 + i * 4);
            *(float4*)&Qs[r * 132 + d0 + i * 4] = tv;
        }
    }

    float acc[4][8];
#pragma unroll
    for (int r = 0; r < 4; r++)
#pragma unroll
        for (int c = 0; c < 8; c++) acc[r][c] = 0.0f;
    float mrow[4] = {-INFINITY, -INFINITY, -INFINITY, -INFINITY};
    float lrow[4] = {0.f, 0.f, 0.f, 0.f};

    const float scale = 0.08838834764831845f;   // 1/sqrt(128)

    for (int kt = 0; kt <= qt; ++kt) {
        __syncthreads();   // prior reads of KT/Vs/Ss done (also covers Q store, iter 0)
        {
            const int r = tid & 63, d0 = (tid >> 6) * 32;
#pragma unroll
            for (int i = 0; i < 8; i++) {
                float4 kv4 = *(const float4*)(Kg + (size_t)(kt * 64 + r) * 1024 + d0 + i * 4);
                KT[(d0 + i * 4 + 0) * 68 + r] = kv4.x;
                KT[(d0 + i * 4 + 1) * 68 + r] = kv4.y;
                KT[(d0 + i * 4 + 2) * 68 + r] = kv4.z;
                KT[(d0 + i * 4 + 3) * 68 + r] = kv4.w;
                float4 vv4 = *(const float4*)(Vg + (size_t)(kt * 64 + r) * 1024 + d0 + i * 4);
                *(float4*)&Vs[r * 132 + d0 + i * 4] = vv4;
            }
        }
        __syncthreads();

        // S = Q @ K^T  (per-thread 4x4 of the 64x64 tile)
        float s[4][4];
#pragma unroll
        for (int r = 0; r < 4; r++)
#pragma unroll
            for (int c = 0; c < 4; c++) s[r][c] = 0.0f;

        for (int d4 = 0; d4 < 128; d4 += 4) {
            float qa[4][4], ka[4][4];
#pragma unroll
            for (int r = 0; r < 4; r++)
                *(float4*)qa[r] = *(const float4*)&Qs[(ty * 4 + r) * 132 + d4];
#pragma unroll
            for (int dd = 0; dd < 4; dd++)
                *(float4*)ka[dd] = *(const float4*)&KT[(d4 + dd) * 68 + tx * 4];
#pragma unroll
            for (int dd = 0; dd < 4; dd++)
#pragma unroll
                for (int r = 0; r < 4; r++)
#pragma unroll
                    for (int c = 0; c < 4; c++)
                        s[r][c] += qa[r][dd] * ka[dd][c];
        }

        const bool diag = (kt == qt);
#pragma unroll
        for (int r = 0; r < 4; r++) {
#pragma unroll
            for (int c = 0; c < 4; c++) {
                float val = s[r][c] * scale;
                if (diag && (tx * 4 + c > ty * 4 + r)) val = -INFINITY;
                s[r][c] = val;
            }
        }

        // online softmax per row (reduce across the 16-lane tx group)
#pragma unroll
        for (int r = 0; r < 4; r++) {
            float mx = fmaxf(fmaxf(s[r][0], s[r][1]), fmaxf(s[r][2], s[r][3]));
#pragma unroll
            for (int o = 8; o >= 1; o >>= 1)
                mx = fmaxf(mx, __shfl_xor_sync(0xffffffffu, mx, o));
            float mnew = fmaxf(mrow[r], mx);
            float alpha = __expf(mrow[r] - mnew);
            mrow[r] = mnew;
            float p0 = __expf(s[r][0] - mnew);
            float p1 = __expf(s[r][1] - mnew);
            float p2 = __expf(s[r][2] - mnew);
            float p3 = __expf(s[r][3] - mnew);
            float rs = p0 + p1 + p2 + p3;
#pragma unroll
            for (int o = 8; o >= 1; o >>= 1)
                rs += __shfl_xor_sync(0xffffffffu, rs, o);
            lrow[r] = lrow[r] * alpha + rs;
#pragma unroll
            for (int c = 0; c < 8; c++) acc[r][c] *= alpha;
            *(float4*)&Ss[(ty * 4 + r) * 68 + tx * 4] = make_float4(p0, p1, p2, p3);
        }
        __syncthreads();

        // O += P @ V
#pragma unroll 4
        for (int kj = 0; kj < 64; kj++) {
            float pr[4];
#pragma unroll
            for (int r = 0; r < 4; r++) pr[r] = Ss[(ty * 4 + r) * 68 + kj];
            float va[8];
            *(float4*)(va)     = *(const float4*)&Vs[kj * 132 + tx * 8];
            *(float4*)(va + 4) = *(const float4*)&Vs[kj * 132 + tx * 8 + 4];
#pragma unroll
            for (int r = 0; r < 4; r++)
#pragma unroll
                for (int c = 0; c < 8; c++)
                    acc[r][c] += pr[r] * va[c];
        }
    }

    // epilogue: normalize and write ctx (layout (B*T, H*D))
#pragma unroll
    for (int r = 0; r < 4; r++) {
        float inv = 1.0f / lrow[r];
        size_t row = (size_t)b * T_ + qt * 64 + ty * 4 + r;
        float* cp = g_ctx + row * (H_ * D_) + h * 128 + tx * 8;
        *(float4*)(cp)     = make_float4(acc[r][0] * inv, acc[r][1] * inv, acc[r][2] * inv, acc[r][3] * inv);
        *(float4*)(cp + 4) = make_float4(acc[r][4] * inv, acc[r][5] * inv, acc[r][6] * inv, acc[r][7] * inv);
    }
    (void)ctx;
}

// ---------------- launch ----------------------------------------------------
extern "C" void kernel_launch(void* const* d_in, const int* in_sizes, int n_in,
                              void* d_out, int out_size)
{
    const float* x  = (const float*)d_in[0];
    // d_in[1] is the causal mask; we implement causality directly
    const float* wq = (const float*)d_in[2];
    const float* wk = (const float*)d_in[3];
    const float* wv = (const float*)d_in[4];
    const float* wo = (const float*)d_in[5];
    float* out = (float*)d_out;

    float *q, *k, *v, *ctx;
    cudaGetSymbolAddress((void**)&q,   g_q);
    cudaGetSymbolAddress((void**)&k,   g_k);
    cudaGetSymbolAddress((void**)&v,   g_v);
    cudaGetSymbolAddress((void**)&ctx, g_ctx);

    // QKV projections
    sgemm128<<<dim3(E_ / 128, ROWS / 128), 256>>>(x, wq, q, ROWS, H_ * D_, E_);
    sgemm128<<<dim3((KVH_ * D_) / 128, ROWS / 128), 256>>>(x, wk, k, ROWS, KVH_ * D_, E_);
    sgemm128<<<dim3((KVH_ * D_) / 128, ROWS / 128), 256>>>(x, wv, v, ROWS, KVH_ * D_, E_);

    // RoPE tables + apply
    rope_init_kernel<<<1, 64>>>();
    rope_table_kernel<<<T_, 64>>>();
    rope_apply_kernel<<<(ROWS * H_ * 64) / 256, 256>>>(q, H_);
    rope_apply_kernel<<<(ROWS * KVH_ * 64) / 256, 256>>>(k, KVH_);

    // Flash attention
    cudaFuncSetAttribute(flash_kernel, cudaFuncAttributeMaxDynamicSharedMemorySize, FL_SMEM);
    flash_kernel<<<dim3(T_ / 64, B_ * H_), 256, FL_SMEM>>>(q, k, v, ctx);

    // Output projection
    sgemm128<<<dim3(E_ / 128, ROWS / 128), 256>>>(ctx, wo, out, ROWS, E_, E_);

    (void)in_sizes; (void)n_in; (void)out_size;
}

// round 13
// speedup vs baseline: 1.5897x; 1.5897x over previous
#include <cuda_runtime.h>
#include <cuda_bf16.h>
#include <math.h>
#include <stdint.h>

#define B_  2
#define T_  2048
#define E_  2048
#define H_  16
#define KVH_ 8
#define D_  128
#define ROWS (B_ * T_)          // 4096

// ---------------- scratch (device globals; no allocation allowed) ----------
__device__ float g_q[(size_t)ROWS * H_ * D_];
__device__ float g_k[(size_t)ROWS * KVH_ * D_];
__device__ float g_v[(size_t)ROWS * KVH_ * D_];
__device__ float g_ctx[(size_t)ROWS * H_ * D_];
__device__ float g_invf[64];
__device__ float g_cos[T_ * 64];
__device__ float g_sin[T_ * 64];

// split-bf16 operands
__device__ __nv_bfloat16 g_xh[(size_t)ROWS * E_];
__device__ __nv_bfloat16 g_xl[(size_t)ROWS * E_];
__device__ __nv_bfloat16 g_wqh[(size_t)E_ * (H_ * D_)];   // transposed [N,K]
__device__ __nv_bfloat16 g_wql[(size_t)E_ * (H_ * D_)];
__device__ __nv_bfloat16 g_wkh[(size_t)E_ * (KVH_ * D_)];
__device__ __nv_bfloat16 g_wkl[(size_t)E_ * (KVH_ * D_)];
__device__ __nv_bfloat16 g_wvh[(size_t)E_ * (KVH_ * D_)];
__device__ __nv_bfloat16 g_wvl[(size_t)E_ * (KVH_ * D_)];
__device__ __nv_bfloat16 g_woh[(size_t)(H_ * D_) * E_];
__device__ __nv_bfloat16 g_wol[(size_t)(H_ * D_) * E_];
__device__ __nv_bfloat16 g_ch[(size_t)ROWS * (H_ * D_)];
__device__ __nv_bfloat16 g_cl[(size_t)ROWS * (H_ * D_)];

// ---------------- helpers ----------------------------------------------------
__device__ __forceinline__ uint32_t smem_u32(const void* p) {
    uint32_t a;
    asm("{ .reg .u64 t; cvta.to.shared.u64 t, %1; cvt.u32.u64 %0, t; }" : "=r"(a) : "l"(p));
    return a;
}
__device__ __forceinline__ void cp16(uint32_t dst, const void* src) {
    asm volatile("cp.async.cg.shared.global [%0], [%1], 16;" :: "r"(dst), "l"(src));
}
__device__ __forceinline__ void ldm_x4(uint32_t* r, uint32_t addr) {
    asm volatile("ldmatrix.sync.aligned.m8n8.x4.shared.b16 {%0,%1,%2,%3}, [%4];"
        : "=r"(r[0]), "=r"(r[1]), "=r"(r[2]), "=r"(r[3]) : "r"(addr));
}
__device__ __forceinline__ void ldm_x2(uint32_t* r, uint32_t addr) {
    asm volatile("ldmatrix.sync.aligned.m8n8.x2.shared.b16 {%0,%1}, [%2];"
        : "=r"(r[0]), "=r"(r[1]) : "r"(addr));
}
__device__ __forceinline__ void mma_bf16(float* d, const uint32_t* a, const uint32_t* b) {
    asm volatile(
        "mma.sync.aligned.m16n8k16.row.col.f32.bf16.bf16.f32 "
        "{%0,%1,%2,%3}, {%4,%5,%6,%7}, {%8,%9}, {%0,%1,%2,%3};"
        : "+f"(d[0]), "+f"(d[1]), "+f"(d[2]), "+f"(d[3])
        : "r"(a[0]), "r"(a[1]), "r"(a[2]), "r"(a[3]), "r"(b[0]), "r"(b[1]));
}

// ---------------- split conversion kernels ----------------------------------
__global__ void conv_split(const float* __restrict__ src, __nv_bfloat16* __restrict__ h,
                           __nv_bfloat16* __restrict__ l, int n2)
{
    int i = blockIdx.x * blockDim.x + threadIdx.x;
    if (i >= n2) return;
    float2 a = ((const float2*)src)[i];
    uint32_t ax = __float_as_uint(a.x), ay = __float_as_uint(a.y);
    uint32_t hp = __byte_perm(ax, ay, 0x7632);        // {hi16(ax), hi16(ay)}
    float hx = __uint_as_float(ax & 0xFFFF0000u);
    float hy = __uint_as_float(ay & 0xFFFF0000u);
    float lx = a.x - hx, ly = a.y - hy;
    uint32_t lp;
    asm("cvt.rn.bf16x2.f32 %0, %1, %2;" : "=r"(lp) : "f"(ly), "f"(lx));
    ((uint32_t*)h)[i] = hp;
    ((uint32_t*)l)[i] = lp;
}

// src [K,N] fp32 -> h/l [N,K] bf16 (transpose + split)
__global__ void convT_split(const float* __restrict__ src, __nv_bfloat16* __restrict__ h,
                            __nv_bfloat16* __restrict__ l, int K, int N)
{
    __shared__ float s[32][33];
    int n0 = blockIdx.x * 32, k0 = blockIdx.y * 32;
    int tx = threadIdx.x, ty = threadIdx.y;   // (32, 8)
#pragma unroll
    for (int i = 0; i < 4; i++)
        s[ty + 8 * i][tx] = src[(size_t)(k0 + ty + 8 * i) * N + n0 + tx];
    __syncthreads();
#pragma unroll
    for (int i = 0; i < 4; i++) {
        int n = n0 + ty + 8 * i;
        float a = s[tx][ty + 8 * i];
        uint32_t ab = __float_as_uint(a);
        float hf = __uint_as_float(ab & 0xFFFF0000u);
        float lf = a - hf;
        unsigned short lb;
        asm("cvt.rn.bf16.f32 %0, %1;" : "=h"(lb) : "f"(lf));
        ((unsigned short*)h)[(size_t)n * K + k0 + tx] = (unsigned short)(ab >> 16);
        ((unsigned short*)l)[(size_t)n * K + k0 + tx] = lb;
    }
}

// ---------------- split-bf16 GEMM via mma.sync (HMMA) ------------------------
// C[M,N] = A[M,K] @ B[K,N]; A as Ah/Al [M,K] bf16, B as BTh/BTl [N,K] bf16.
// Tile 128x128, BK=64, 8 warps (2x4), each warp 64x32 (4x4 m16n8k16 tiles).
// Smem row stride: 72 bf16 = 144 B (conflict-free for ldmatrix & cp.async).
#define GS_STRIDE 144                       // bytes per row
#define GS_MAT    (128 * GS_STRIDE)         // 18432 B per matrix
#define GEMM_SMEM (4 * GS_MAT)              // 73728 B

__global__ __launch_bounds__(256, 2)
void gemm_split(const __nv_bfloat16* __restrict__ Ah, const __nv_bfloat16* __restrict__ Al,
                const __nv_bfloat16* __restrict__ Bh, const __nv_bfloat16* __restrict__ Bl,
                float* __restrict__ C, int M, int N, int K)
{
    extern __shared__ __align__(128) unsigned char gsm[];
    const uint32_t sb  = smem_u32(gsm);
    const uint32_t sAh = sb, sAl = sb + GS_MAT, sBh = sb + 2 * GS_MAT, sBl = sb + 3 * GS_MAT;

    const int tid = threadIdx.x, wid = tid >> 5, lane = tid & 31;
    const int bx = blockIdx.x, by = blockIdx.y;
    const int wm = wid >> 2, wn = wid & 3;          // warp 64-row block, 32-col block

    float acc[4][4][4];
#pragma unroll
    for (int mt = 0; mt < 4; mt++)
#pragma unroll
        for (int nt = 0; nt < 4; nt++)
#pragma unroll
            for (int r = 0; r < 4; r++) acc[mt][nt][r] = 0.0f;

    // copy geometry: 128 rows x 8 chunks of 16B per matrix; thread -> (r0=tid>>3, c=tid&7)
    const int cch = tid & 7, r0 = tid >> 3;

    // ldmatrix addresses (bytes, within a matrix)
    const uint32_t a_row = (uint32_t)(wm * 64 + (lane & 15));
    const uint32_t a_koff = (uint32_t)((lane >> 4) * 16);
    const uint32_t b_row = (uint32_t)(wn * 32 + (lane & 7));
    const uint32_t b_koff = (uint32_t)(((lane >> 3) & 1) * 16);

    for (int kc = 0; kc < K; kc += 64) {
#pragma unroll
        for (int i = 0; i < 4; i++) {
            int r = r0 + 32 * i;
            uint32_t dst = (uint32_t)(r * GS_STRIDE + cch * 16);
            size_t asrc = (size_t)(by * 128 + r) * K + kc + cch * 8;
            size_t bsrc = (size_t)(bx * 128 + r) * K + kc + cch * 8;
            cp16(sAh + dst, Ah + asrc);
            cp16(sAl + dst, Al + asrc);
            cp16(sBh + dst, Bh + bsrc);
            cp16(sBl + dst, Bl + bsrc);
        }
        asm volatile("cp.async.commit_group;" ::: "memory");
        asm volatile("cp.async.wait_group 0;" ::: "memory");
        __syncthreads();

#pragma unroll
        for (int k16 = 0; k16 < 4; k16++) {
            const uint32_t koff = (uint32_t)(k16 * 32);
            uint32_t bh[4][2], bl[4][2];
#pragma unroll
            for (int nt = 0; nt < 4; nt++) {
                uint32_t baddr = (b_row + nt * 8) * GS_STRIDE + koff + b_koff;
                ldm_x2(bh[nt], sBh + baddr);
                ldm_x2(bl[nt], sBl + baddr);
            }
#pragma unroll
            for (int mt = 0; mt < 4; mt++) {
                uint32_t aaddr = (a_row + mt * 16) * GS_STRIDE + koff + a_koff;
                uint32_t ah[4], al[4];
                ldm_x4(ah, sAh + aaddr);
                ldm_x4(al, sAl + aaddr);
#pragma unroll
                for (int nt = 0; nt < 4; nt++) {
                    mma_bf16(acc[mt][nt], ah, bh[nt]);   // hi*hi
                    mma_bf16(acc[mt][nt], ah, bl[nt]);   // hi*lo
                    mma_bf16(acc[mt][nt], al, bh[nt]);   // lo*hi
                }
            }
        }
        __syncthreads();
    }

    // epilogue: fragment -> C (fp32)
    const int erow = by * 128 + wm * 64 + (lane >> 2);
    const int ecol = bx * 128 + wn * 32 + (lane & 3) * 2;
#pragma unroll
    for (int mt = 0; mt < 4; mt++) {
#pragma unroll
        for (int nt = 0; nt < 4; nt++) {
            float* p0 = C + (size_t)(erow + mt * 16) * N + ecol + nt * 8;
            float* p1 = C + (size_t)(erow + mt * 16 + 8) * N + ecol + nt * 8;
            *(float2*)p0 = make_float2(acc[mt][nt][0], acc[mt][nt][1]);
            *(float2*)p1 = make_float2(acc[mt][nt][2], acc[mt][nt][3]);
        }
    }
}

// ---------------- RoPE -------------------------------------------------------
__global__ void rope_init_kernel()
{
    int j = threadIdx.x;
    if (j < 64)
        g_invf[j] = (float)pow(10000.0, -(double)j / 64.0);
}

__global__ void rope_table_kernel()
{
    int t = blockIdx.x;
    int j = threadIdx.x;
    float f = (float)t * g_invf[j];
    float s, c;
    sincosf(f, &s, &c);
    g_cos[t * 64 + j] = c;
    g_sin[t * 64 + j] = s;
}

__global__ void rope_apply_kernel(float* __restrict__ a, int nh)
{
    int pidx = blockIdx.x * blockDim.x + threadIdx.x;
    int j    = pidx & 63;
    int head = (pidx >> 6) % nh;
    int row  = pidx / (nh * 64);
    int t    = row & (T_ - 1);

    size_t off = (size_t)row * nh * 128 + head * 128 + 2 * j;
    float2 xv = *(float2*)(a + off);
    float c = g_cos[t * 64 + j];
    float s = g_sin[t * 64 + j];
    float2 o;
    o.x = xv.x * c - xv.y * s;
    o.y = xv.x * s + xv.y * c;
    *(float2*)(a + off) = o;
}

// ---------------- Flash attention (fp32 SIMT, unchanged) ---------------------
#define FL_SMEM ((64 * 132 + 128 * 68 + 64 * 132 + 64 * 68) * 4)

__global__ __launch_bounds__(256, 1)
void flash_kernel(const float* __restrict__ Q, const float* __restrict__ K,
                  const float* __restrict__ V, float* __restrict__ ctx)
{
    extern __shared__ __align__(16) float sm[];
    float* Qs = sm;
    float* KT = sm + 64 * 132;
    float* Vs = KT + 128 * 68;
    float* Ss = Vs + 64 * 132;

    const int qt = gridDim.x - 1 - blockIdx.x;
    const int bh = blockIdx.y;
    const int b = bh >> 4, h = bh & 15;
    const int kvh = h >> 1;
    const int tid = threadIdx.x;
    const int ty = tid >> 4, tx = tid & 15;

    const float* Qg = Q + (size_t)b * T_ * 2048 + (size_t)h * 128;
    const float* Kg = K + (size_t)b * T_ * 1024 + (size_t)kvh * 128;
    const float* Vg = V + (size_t)b * T_ * 1024 + (size_t)kvh * 128;

    {
        const int r = tid & 63, d0 = (tid >> 6) * 32;
#pragma unroll
        for (int i = 0; i < 8; i++) {
            float4 tv = *(const float4*)(Qg + (size_t)(qt * 64 + r) * 2048 + d0 + i * 4);
            *(float4*)&Qs[r * 132 + d0 + i * 4] = tv;
        }
    }

    float acc[4][8];
#pragma unroll
    for (int r = 0; r < 4; r++)
#pragma unroll
        for (int c = 0; c < 8; c++) acc[r][c] = 0.0f;
    float mrow[4] = {-INFINITY, -INFINITY, -INFINITY, -INFINITY};
    float lrow[4] = {0.f, 0.f, 0.f, 0.f};

    const float scale = 0.08838834764831845f;

    for (int kt = 0; kt <= qt; ++kt) {
        __syncthreads();
        {
            const int r = tid & 63, d0 = (tid >> 6) * 32;
#pragma unroll
            for (int i = 0; i < 8; i++) {
                float4 kv4 = *(const float4*)(Kg + (size_t)(kt * 64 + r) * 1024 + d0 + i * 4);
                KT[(d0 + i * 4 + 0) * 68 + r] = kv4.x;
                KT[(d0 + i * 4 + 1) * 68 + r] = kv4.y;
                KT[(d0 + i * 4 + 2) * 68 + r] = kv4.z;
                KT[(d0 + i * 4 + 3) * 68 + r] = kv4.w;
                float4 vv4 = *(const float4*)(Vg + (size_t)(kt * 64 + r) * 1024 + d0 + i * 4);
                *(float4*)&Vs[r * 132 + d0 + i * 4] = vv4;
            }
        }
        __syncthreads();

        float s[4][4];
#pragma unroll
        for (int r = 0; r < 4; r++)
#pragma unroll
            for (int c = 0; c < 4; c++) s[r][c] = 0.0f;

        for (int d4 = 0; d4 < 128; d4 += 4) {
            float qa[4][4], ka[4][4];
#pragma unroll
            for (int r = 0; r < 4; r++)
                *(float4*)qa[r] = *(const float4*)&Qs[(ty * 4 + r) * 132 + d4];
#pragma unroll
            for (int dd = 0; dd < 4; dd++)
                *(float4*)ka[dd] = *(const float4*)&KT[(d4 + dd) * 68 + tx * 4];
#pragma unroll
            for (int dd = 0; dd < 4; dd++)
#pragma unroll
                for (int r = 0; r < 4; r++)
#pragma unroll
                    for (int c = 0; c < 4; c++)
                        s[r][c] += qa[r][dd] * ka[dd][c];
        }

        const bool diag = (kt == qt);
#pragma unroll
        for (int r = 0; r < 4; r++) {
#pragma unroll
            for (int c = 0; c < 4; c++) {
                float val = s[r][c] * scale;
                if (diag && (tx * 4 + c > ty * 4 + r)) val = -INFINITY;
                s[r][c] = val;
            }
        }

#pragma unroll
        for (int r = 0; r < 4; r++) {
            float mx = fmaxf(fmaxf(s[r][0], s[r][1]), fmaxf(s[r][2], s[r][3]));
#pragma unroll
            for (int o = 8; o >= 1; o >>= 1)
                mx = fmaxf(mx, __shfl_xor_sync(0xffffffffu, mx, o));
            float mnew = fmaxf(mrow[r], mx);
            float alpha = __expf(mrow[r] - mnew);
            mrow[r] = mnew;
            float p0 = __expf(s[r][0] - mnew);
            float p1 = __expf(s[r][1] - mnew);
            float p2 = __expf(s[r][2] - mnew);
            float p3 = __expf(s[r][3] - mnew);
            float rs = p0 + p1 + p2 + p3;
#pragma unroll
            for (int o = 8; o >= 1; o >>= 1)
                rs += __shfl_xor_sync(0xffffffffu, rs, o);
            lrow[r] = lrow[r] * alpha + rs;
#pragma unroll
            for (int c = 0; c < 8; c++) acc[r][c] *= alpha;
            *(float4*)&Ss[(ty * 4 + r) * 68 + tx * 4] = make_float4(p0, p1, p2, p3);
        }
        __syncthreads();

#pragma unroll 4
        for (int kj = 0; kj < 64; kj++) {
            float pr[4];
#pragma unroll
            for (int r = 0; r < 4; r++) pr[r] = Ss[(ty * 4 + r) * 68 + kj];
            float va[8];
            *(float4*)(va)     = *(const float4*)&Vs[kj * 132 + tx * 8];
            *(float4*)(va + 4) = *(const float4*)&Vs[kj * 132 + tx * 8 + 4];
#pragma unroll
            for (int r = 0; r < 4; r++)
#pragma unroll
                for (int c = 0; c < 8; c++)
                    acc[r][c] += pr[r] * va[c];
        }
    }

#pragma unroll
    for (int r = 0; r < 4; r++) {
        float inv = 1.0f / lrow[r];
        size_t row = (size_t)b * T_ + qt * 64 + ty * 4 + r;
        float* cp = g_ctx + row * (H_ * D_) + h * 128 + tx * 8;
        *(float4*)(cp)     = make_float4(acc[r][0] * inv, acc[r][1] * inv, acc[r][2] * inv, acc[r][3] * inv);
        *(float4*)(cp + 4) = make_float4(acc[r][4] * inv, acc[r][5] * inv, acc[r][6] * inv, acc[r][7] * inv);
    }
    (void)ctx;
}

// ---------------- launch -----------------------------------------------------
extern "C" void kernel_launch(void* const* d_in, const int* in_sizes, int n_in,
                              void* d_out, int out_size)
{
    const float* x  = (const float*)d_in[0];
    const float* wq = (const float*)d_in[2];
    const float* wk = (const float*)d_in[3];
    const float* wv = (const float*)d_in[4];
    const float* wo = (const float*)d_in[5];
    float* out = (float*)d_out;

    float *q, *k, *v, *ctx;
    cudaGetSymbolAddress((void**)&q,   g_q);
    cudaGetSymbolAddress((void**)&k,   g_k);
    cudaGetSymbolAddress((void**)&v,   g_v);
    cudaGetSymbolAddress((void**)&ctx, g_ctx);
    __nv_bfloat16 *xh, *xl, *wqh, *wql, *wkh, *wkl, *wvh, *wvl, *woh, *wol, *ch, *cl;
    cudaGetSymbolAddress((void**)&xh,  g_xh);   cudaGetSymbolAddress((void**)&xl,  g_xl);
    cudaGetSymbolAddress((void**)&wqh, g_wqh);  cudaGetSymbolAddress((void**)&wql, g_wql);
    cudaGetSymbolAddress((void**)&wkh, g_wkh);  cudaGetSymbolAddress((void**)&wkl, g_wkl);
    cudaGetSymbolAddress((void**)&wvh, g_wvh);  cudaGetSymbolAddress((void**)&wvl, g_wvl);
    cudaGetSymbolAddress((void**)&woh, g_woh);  cudaGetSymbolAddress((void**)&wol, g_wol);
    cudaGetSymbolAddress((void**)&ch,  g_ch);   cudaGetSymbolAddress((void**)&cl,  g_cl);

    cudaFuncSetAttribute(gemm_split, cudaFuncAttributeMaxDynamicSharedMemorySize, GEMM_SMEM);
    cudaFuncSetAttribute(flash_kernel, cudaFuncAttributeMaxDynamicSharedMemorySize, FL_SMEM);

    // split conversions
    conv_split<<<(ROWS * E_ / 2 + 255) / 256, 256>>>(x, xh, xl, ROWS * E_ / 2);
    convT_split<<<dim3((H_ * D_) / 32, E_ / 32), dim3(32, 8)>>>(wq, wqh, wql, E_, H_ * D_);
    convT_split<<<dim3((KVH_ * D_) / 32, E_ / 32), dim3(32, 8)>>>(wk, wkh, wkl, E_, KVH_ * D_);
    convT_split<<<dim3((KVH_ * D_) / 32, E_ / 32), dim3(32, 8)>>>(wv, wvh, wvl, E_, KVH_ * D_);
    convT_split<<<dim3(E_ / 32, (H_ * D_) / 32), dim3(32, 8)>>>(wo, woh, wol, H_ * D_, E_);

    // QKV projections on tensor cores (mma.sync)
    gemm_split<<<dim3((H_ * D_) / 128, ROWS / 128), 256, GEMM_SMEM>>>(xh, xl, wqh, wql, q, ROWS, H_ * D_, E_);
    gemm_split<<<dim3((KVH_ * D_) / 128, ROWS / 128), 256, GEMM_SMEM>>>(xh, xl, wkh, wkl, k, ROWS, KVH_ * D_, E_);
    gemm_split<<<dim3((KVH_ * D_) / 128, ROWS / 128), 256, GEMM_SMEM>>>(xh, xl, wvh, wvl, v, ROWS, KVH_ * D_, E_);

    // RoPE
    rope_init_kernel<<<1, 64>>>();
    rope_table_kernel<<<T_, 64>>>();
    rope_apply_kernel<<<(ROWS * H_ * 64) / 256, 256>>>(q, H_);
    rope_apply_kernel<<<(ROWS * KVH_ * 64) / 256, 256>>>(k, KVH_);

    // Flash attention (fp32)
    flash_kernel<<<dim3(T_ / 64, B_ * H_), 256, FL_SMEM>>>(q, k, v, ctx);

    // Output projection on tensor cores
    conv_split<<<(ROWS * (H_ * D_) / 2 + 255) / 256, 256>>>(ctx, ch, cl, ROWS * (H_ * D_) / 2);
    gemm_split<<<dim3(E_ / 128, ROWS / 128), 256, GEMM_SMEM>>>(ch, cl, woh, wol, out, ROWS, E_, H_ * D_);

    (void)in_sizes; (void)n_in; (void)out_size;
}

// round 14
// speedup vs baseline: 2.8066x; 1.7655x over previous
#include <cuda_runtime.h>
#include <cuda_bf16.h>
#include <math.h>
#include <stdint.h>

#define B_  2
#define T_  2048
#define E_  2048
#define H_  16
#define KVH_ 8
#define D_  128
#define ROWS (B_ * T_)          // 4096

// ---------------- scratch (device globals; no allocation allowed) ----------
__device__ float g_q[(size_t)ROWS * H_ * D_];
__device__ float g_k[(size_t)ROWS * KVH_ * D_];
__device__ float g_v[(size_t)ROWS * KVH_ * D_];
__device__ float g_ctx[(size_t)ROWS * H_ * D_];
__device__ float g_invf[64];
__device__ float g_cos[T_ * 64];
__device__ float g_sin[T_ * 64];

// split-bf16 operands
__device__ __nv_bfloat16 g_xh[(size_t)ROWS * E_];
__device__ __nv_bfloat16 g_xl[(size_t)ROWS * E_];
__device__ __nv_bfloat16 g_wqh[(size_t)E_ * (H_ * D_)];
__device__ __nv_bfloat16 g_wql[(size_t)E_ * (H_ * D_)];
__device__ __nv_bfloat16 g_wkh[(size_t)E_ * (KVH_ * D_)];
__device__ __nv_bfloat16 g_wkl[(size_t)E_ * (KVH_ * D_)];
__device__ __nv_bfloat16 g_wvh[(size_t)E_ * (KVH_ * D_)];
__device__ __nv_bfloat16 g_wvl[(size_t)E_ * (KVH_ * D_)];
__device__ __nv_bfloat16 g_woh[(size_t)(H_ * D_) * E_];
__device__ __nv_bfloat16 g_wol[(size_t)(H_ * D_) * E_];
__device__ __nv_bfloat16 g_ch[(size_t)ROWS * (H_ * D_)];
__device__ __nv_bfloat16 g_cl[(size_t)ROWS * (H_ * D_)];
// attention split operands
__device__ __nv_bfloat16 g_qhb[(size_t)ROWS * H_ * D_];
__device__ __nv_bfloat16 g_qlb[(size_t)ROWS * H_ * D_];
__device__ __nv_bfloat16 g_khb[(size_t)ROWS * KVH_ * D_];
__device__ __nv_bfloat16 g_klb[(size_t)ROWS * KVH_ * D_];
__device__ __nv_bfloat16 g_vhb[(size_t)ROWS * KVH_ * D_];
__device__ __nv_bfloat16 g_vlb[(size_t)ROWS * KVH_ * D_];

// ---------------- helpers ----------------------------------------------------
__device__ __forceinline__ uint32_t smem_u32(const void* p) {
    uint32_t a;
    asm("{ .reg .u64 t; cvta.to.shared.u64 t, %1; cvt.u32.u64 %0, t; }" : "=r"(a) : "l"(p));
    return a;
}
__device__ __forceinline__ void cp16(uint32_t dst, const void* src) {
    asm volatile("cp.async.cg.shared.global [%0], [%1], 16;" :: "r"(dst), "l"(src));
}
__device__ __forceinline__ void ldm_x4(uint32_t* r, uint32_t addr) {
    asm volatile("ldmatrix.sync.aligned.m8n8.x4.shared.b16 {%0,%1,%2,%3}, [%4];"
        : "=r"(r[0]), "=r"(r[1]), "=r"(r[2]), "=r"(r[3]) : "r"(addr));
}
__device__ __forceinline__ void ldm_x2(uint32_t* r, uint32_t addr) {
    asm volatile("ldmatrix.sync.aligned.m8n8.x2.shared.b16 {%0,%1}, [%2];"
        : "=r"(r[0]), "=r"(r[1]) : "r"(addr));
}
__device__ __forceinline__ void ldm_x2t(uint32_t* r, uint32_t addr) {
    asm volatile("ldmatrix.sync.aligned.m8n8.x2.trans.shared.b16 {%0,%1}, [%2];"
        : "=r"(r[0]), "=r"(r[1]) : "r"(addr));
}
__device__ __forceinline__ void mma_bf16(float* d, const uint32_t* a, const uint32_t* b) {
    asm volatile(
        "mma.sync.aligned.m16n8k16.row.col.f32.bf16.bf16.f32 "
        "{%0,%1,%2,%3}, {%4,%5,%6,%7}, {%8,%9}, {%0,%1,%2,%3};"
        : "+f"(d[0]), "+f"(d[1]), "+f"(d[2]), "+f"(d[3])
        : "r"(a[0]), "r"(a[1]), "r"(a[2]), "r"(a[3]), "r"(b[0]), "r"(b[1]));
}
__device__ __forceinline__ uint32_t pack_bf16(float lo, float hi) {
    uint32_t r;
    asm("cvt.rn.bf16x2.f32 %0, %1, %2;" : "=r"(r) : "f"(hi), "f"(lo));
    return r;
}
__device__ __forceinline__ float lo_of(uint32_t p) { return __uint_as_float(p << 16); }
__device__ __forceinline__ float hi_of(uint32_t p) { return __uint_as_float(p & 0xFFFF0000u); }

// ---------------- split conversion kernels ----------------------------------
__global__ void conv_split(const float* __restrict__ src, __nv_bfloat16* __restrict__ h,
                           __nv_bfloat16* __restrict__ l, int n2)
{
    int i = blockIdx.x * blockDim.x + threadIdx.x;
    if (i >= n2) return;
    float2 a = ((const float2*)src)[i];
    uint32_t ax = __float_as_uint(a.x), ay = __float_as_uint(a.y);
    uint32_t hp = __byte_perm(ax, ay, 0x7632);
    float hx = __uint_as_float(ax & 0xFFFF0000u);
    float hy = __uint_as_float(ay & 0xFFFF0000u);
    float lx = a.x - hx, ly = a.y - hy;
    uint32_t lp;
    asm("cvt.rn.bf16x2.f32 %0, %1, %2;" : "=r"(lp) : "f"(ly), "f"(lx));
    ((uint32_t*)h)[i] = hp;
    ((uint32_t*)l)[i] = lp;
}

__global__ void convT_split(const float* __restrict__ src, __nv_bfloat16* __restrict__ h,
                            __nv_bfloat16* __restrict__ l, int K, int N)
{
    __shared__ float s[32][33];
    int n0 = blockIdx.x * 32, k0 = blockIdx.y * 32;
    int tx = threadIdx.x, ty = threadIdx.y;
#pragma unroll
    for (int i = 0; i < 4; i++)
        s[ty + 8 * i][tx] = src[(size_t)(k0 + ty + 8 * i) * N + n0 + tx];
    __syncthreads();
#pragma unroll
    for (int i = 0; i < 4; i++) {
        int n = n0 + ty + 8 * i;
        float a = s[tx][ty + 8 * i];
        uint32_t ab = __float_as_uint(a);
        float hf = __uint_as_float(ab & 0xFFFF0000u);
        float lf = a - hf;
        unsigned short lb;
        asm("cvt.rn.bf16.f32 %0, %1;" : "=h"(lb) : "f"(lf));
        ((unsigned short*)h)[(size_t)n * K + k0 + tx] = (unsigned short)(ab >> 16);
        ((unsigned short*)l)[(size_t)n * K + k0 + tx] = lb;
    }
}

// ---------------- split-bf16 GEMM via mma.sync (unchanged from R13) ----------
#define GS_STRIDE 144
#define GS_MAT    (128 * GS_STRIDE)
#define GEMM_SMEM (4 * GS_MAT)

__global__ __launch_bounds__(256, 2)
void gemm_split(const __nv_bfloat16* __restrict__ Ah, const __nv_bfloat16* __restrict__ Al,
                const __nv_bfloat16* __restrict__ Bh, const __nv_bfloat16* __restrict__ Bl,
                float* __restrict__ C, int M, int N, int K)
{
    extern __shared__ __align__(128) unsigned char gsm[];
    const uint32_t sb  = smem_u32(gsm);
    const uint32_t sAh = sb, sAl = sb + GS_MAT, sBh = sb + 2 * GS_MAT, sBl = sb + 3 * GS_MAT;

    const int tid = threadIdx.x, wid = tid >> 5, lane = tid & 31;
    const int bx = blockIdx.x, by = blockIdx.y;
    const int wm = wid >> 2, wn = wid & 3;

    float acc[4][4][4];
#pragma unroll
    for (int mt = 0; mt < 4; mt++)
#pragma unroll
        for (int nt = 0; nt < 4; nt++)
#pragma unroll
            for (int r = 0; r < 4; r++) acc[mt][nt][r] = 0.0f;

    const int cch = tid & 7, r0 = tid >> 3;
    const uint32_t a_row = (uint32_t)(wm * 64 + (lane & 15));
    const uint32_t a_koff = (uint32_t)((lane >> 4) * 16);
    const uint32_t b_row = (uint32_t)(wn * 32 + (lane & 7));
    const uint32_t b_koff = (uint32_t)(((lane >> 3) & 1) * 16);

    for (int kc = 0; kc < K; kc += 64) {
#pragma unroll
        for (int i = 0; i < 4; i++) {
            int r = r0 + 32 * i;
            uint32_t dst = (uint32_t)(r * GS_STRIDE + cch * 16);
            size_t asrc = (size_t)(by * 128 + r) * K + kc + cch * 8;
            size_t bsrc = (size_t)(bx * 128 + r) * K + kc + cch * 8;
            cp16(sAh + dst, Ah + asrc);
            cp16(sAl + dst, Al + asrc);
            cp16(sBh + dst, Bh + bsrc);
            cp16(sBl + dst, Bl + bsrc);
        }
        asm volatile("cp.async.commit_group;" ::: "memory");
        asm volatile("cp.async.wait_group 0;" ::: "memory");
        __syncthreads();

#pragma unroll
        for (int k16 = 0; k16 < 4; k16++) {
            const uint32_t koff = (uint32_t)(k16 * 32);
            uint32_t bh[4][2], bl[4][2];
#pragma unroll
            for (int nt = 0; nt < 4; nt++) {
                uint32_t baddr = (b_row + nt * 8) * GS_STRIDE + koff + b_koff;
                ldm_x2(bh[nt], sBh + baddr);
                ldm_x2(bl[nt], sBl + baddr);
            }
#pragma unroll
            for (int mt = 0; mt < 4; mt++) {
                uint32_t aaddr = (a_row + mt * 16) * GS_STRIDE + koff + a_koff;
                uint32_t ah[4], al[4];
                ldm_x4(ah, sAh + aaddr);
                ldm_x4(al, sAl + aaddr);
#pragma unroll
                for (int nt = 0; nt < 4; nt++) {
                    mma_bf16(acc[mt][nt], ah, bh[nt]);
                    mma_bf16(acc[mt][nt], ah, bl[nt]);
                    mma_bf16(acc[mt][nt], al, bh[nt]);
                }
            }
        }
        __syncthreads();
    }

    const int erow = by * 128 + wm * 64 + (lane >> 2);
    const int ecol = bx * 128 + wn * 32 + (lane & 3) * 2;
#pragma unroll
    for (int mt = 0; mt < 4; mt++) {
#pragma unroll
        for (int nt = 0; nt < 4; nt++) {
            float* p0 = C + (size_t)(erow + mt * 16) * N + ecol + nt * 8;
            float* p1 = C + (size_t)(erow + mt * 16 + 8) * N + ecol + nt * 8;
            *(float2*)p0 = make_float2(acc[mt][nt][0], acc[mt][nt][1]);
            *(float2*)p1 = make_float2(acc[mt][nt][2], acc[mt][nt][3]);
        }
    }
}

// ---------------- RoPE -------------------------------------------------------
__global__ void rope_init_kernel()
{
    int j = threadIdx.x;
    if (j < 64)
        g_invf[j] = (float)pow(10000.0, -(double)j / 64.0);
}

__global__ void rope_table_kernel()
{
    int t = blockIdx.x;
    int j = threadIdx.x;
    float f = (float)t * g_invf[j];
    float s, c;
    sincosf(f, &s, &c);
    g_cos[t * 64 + j] = c;
    g_sin[t * 64 + j] = s;
}

__global__ void rope_apply_kernel(float* __restrict__ a, int nh)
{
    int pidx = blockIdx.x * blockDim.x + threadIdx.x;
    int j    = pidx & 63;
    int head = (pidx >> 6) % nh;
    int row  = pidx / (nh * 64);
    int t    = row & (T_ - 1);

    size_t off = (size_t)row * nh * 128 + head * 128 + 2 * j;
    float2 xv = *(float2*)(a + off);
    float c = g_cos[t * 64 + j];
    float s = g_sin[t * 64 + j];
    float2 o;
    o.x = xv.x * c - xv.y * s;
    o.y = xv.x * s + xv.y * c;
    *(float2*)(a + off) = o;
}

// ---------------- Flash attention via mma.sync (split-bf16) ------------------
// BQ=64, BK=64, D=128, 128 threads (4 warps, 16 q-rows each).
// smem: Qh,Ql,Kh,Kl,Vh,Vl each 64 rows x 256B data, stride 272B.
#define FA_STRIDE 272
#define FA_MAT    (64 * FA_STRIDE)      // 17408 B
#define FA_SMEM   (6 * FA_MAT)          // 104448 B

__global__ __launch_bounds__(128)
void flash_mma(const __nv_bfloat16* __restrict__ Qh, const __nv_bfloat16* __restrict__ Ql,
               const __nv_bfloat16* __restrict__ Kh, const __nv_bfloat16* __restrict__ Kl,
               const __nv_bfloat16* __restrict__ Vh, const __nv_bfloat16* __restrict__ Vl)
{
    extern __shared__ __align__(128) unsigned char fsm[];
    const uint32_t sb  = smem_u32(fsm);
    const uint32_t sQh = sb,            sQl = sb + FA_MAT;
    const uint32_t sKh = sb + 2*FA_MAT, sKl = sb + 3*FA_MAT;
    const uint32_t sVh = sb + 4*FA_MAT, sVl = sb + 5*FA_MAT;

    const int qt = gridDim.x - 1 - blockIdx.x;   // heavy tiles first
    const int bh = blockIdx.y;
    const int b = bh >> 4, h = bh & 15;
    const int kvh = h >> 1;
    const int tid = threadIdx.x, wid = tid >> 5, lane = tid & 31;

    // Q tile load (once): 64 rows x 16 chunks of 16B per matrix
    for (int s = tid; s < 1024; s += 128) {
        int r = s >> 4, c = s & 15;
        size_t src = (size_t)(b * T_ + qt * 64 + r) * (H_ * D_) + h * 128 + c * 8;
        uint32_t dst = (uint32_t)(r * FA_STRIDE + c * 16);
        cp16(sQh + dst, Qh + src);
        cp16(sQl + dst, Ql + src);
    }

    float oc[16][4];
#pragma unroll
    for (int nt = 0; nt < 16; nt++)
#pragma unroll
        for (int e = 0; e < 4; e++) oc[nt][e] = 0.0f;
    float m0 = -INFINITY, m1 = -INFINITY, l0 = 0.0f, l1 = 0.0f;

    const float scale = 0.08838834764831845f;
    const int row0 = qt * 64 + wid * 16 + (lane >> 2);   // global q row (first half)
    const int colb = 2 * (lane & 3);                     // col base within 8-tile

    // ldmatrix address components
    const uint32_t qrow_off = (uint32_t)((wid * 16 + (lane & 15)) * FA_STRIDE);
    const uint32_t a_koff   = (uint32_t)((lane >> 4) * 16);
    const uint32_t krow_b   = (uint32_t)((lane & 7) * FA_STRIDE);
    const uint32_t b_koff   = (uint32_t)(((lane >> 3) & 1) * 16);
    const uint32_t vrow_b   = (uint32_t)((((lane >> 3) & 1) * 8 + (lane & 7)) * FA_STRIDE);

    for (int kt = 0; kt <= qt; ++kt) {
        if (kt > 0) __syncthreads();    // prior K/V reads done
        for (int s = tid; s < 1024; s += 128) {
            int r = s >> 4, c = s & 15;
            size_t src = (size_t)(b * T_ + kt * 64 + r) * (KVH_ * D_) + kvh * 128 + c * 8;
            uint32_t dst = (uint32_t)(r * FA_STRIDE + c * 16);
            cp16(sKh + dst, Kh + src);
            cp16(sKl + dst, Kl + src);
            cp16(sVh + dst, Vh + src);
            cp16(sVl + dst, Vl + src);
        }
        asm volatile("cp.async.commit_group;" ::: "memory");
        asm volatile("cp.async.wait_group 0;" ::: "memory");
        __syncthreads();

        // ---- S = Q @ K^T (split 3-term) ----
        float sc[8][4];
#pragma unroll
        for (int nt = 0; nt < 8; nt++)
#pragma unroll
            for (int e = 0; e < 4; e++) sc[nt][e] = 0.0f;

#pragma unroll
        for (int ks = 0; ks < 8; ks++) {
            uint32_t koff = (uint32_t)(ks * 32);
            uint32_t qhf[4], qlf[4];
            ldm_x4(qhf, sQh + qrow_off + koff + a_koff);
            ldm_x4(qlf, sQl + qrow_off + koff + a_koff);
#pragma unroll
            for (int nt = 0; nt < 8; nt++) {
                uint32_t khf[2], klf[2];
                uint32_t baddr = (uint32_t)(nt * 8 * FA_STRIDE) + krow_b + koff + b_koff;
                ldm_x2(khf, sKh + baddr);
                ldm_x2(klf, sKl + baddr);
                mma_bf16(sc[nt], qhf, khf);
                mma_bf16(sc[nt], qhf, klf);
                mma_bf16(sc[nt], qlf, khf);
            }
        }

        // ---- scale + causal mask ----
        const bool diag = (kt == qt);
#pragma unroll
        for (int nt = 0; nt < 8; nt++) {
#pragma unroll
            for (int e = 0; e < 4; e++) {
                float val = sc[nt][e] * scale;
                if (diag) {
                    int col = kt * 64 + nt * 8 + colb + (e & 1);
                    int row = row0 + ((e >> 1) << 3);
                    if (col > row) val = -INFINITY;
                }
                sc[nt][e] = val;
            }
        }

        // ---- online softmax (rows r0 and r0+8) ----
        float mx0 = -INFINITY, mx1 = -INFINITY;
#pragma unroll
        for (int nt = 0; nt < 8; nt++) {
            mx0 = fmaxf(mx0, fmaxf(sc[nt][0], sc[nt][1]));
            mx1 = fmaxf(mx1, fmaxf(sc[nt][2], sc[nt][3]));
        }
        mx0 = fmaxf(mx0, __shfl_xor_sync(0xffffffffu, mx0, 1));
        mx0 = fmaxf(mx0, __shfl_xor_sync(0xffffffffu, mx0, 2));
        mx1 = fmaxf(mx1, __shfl_xor_sync(0xffffffffu, mx1, 1));
        mx1 = fmaxf(mx1, __shfl_xor_sync(0xffffffffu, mx1, 2));

        float mn0 = fmaxf(m0, mx0), mn1 = fmaxf(m1, mx1);
        float al0 = __expf(m0 - mn0), al1 = __expf(m1 - mn1);
        m0 = mn0; m1 = mn1;

        float rs0 = 0.0f, rs1 = 0.0f;
#pragma unroll
        for (int nt = 0; nt < 8; nt++) {
            sc[nt][0] = __expf(sc[nt][0] - m0);
            sc[nt][1] = __expf(sc[nt][1] - m0);
            sc[nt][2] = __expf(sc[nt][2] - m1);
            sc[nt][3] = __expf(sc[nt][3] - m1);
            rs0 += sc[nt][0] + sc[nt][1];
            rs1 += sc[nt][2] + sc[nt][3];
        }
        rs0 += __shfl_xor_sync(0xffffffffu, rs0, 1);
        rs0 += __shfl_xor_sync(0xffffffffu, rs0, 2);
        rs1 += __shfl_xor_sync(0xffffffffu, rs1, 1);
        rs1 += __shfl_xor_sync(0xffffffffu, rs1, 2);
        l0 = l0 * al0 + rs0;
        l1 = l1 * al1 + rs1;

#pragma unroll
        for (int nt = 0; nt < 16; nt++) {
            oc[nt][0] *= al0; oc[nt][1] *= al0;
            oc[nt][2] *= al1; oc[nt][3] *= al1;
        }

        // ---- O += P @ V (split P and V, 3-term) ----
#pragma unroll
        for (int ktv = 0; ktv < 4; ktv++) {
            float* s0 = sc[2 * ktv];
            float* s1 = sc[2 * ktv + 1];
            uint32_t ph[4], pl[4];
            ph[0] = pack_bf16(s0[0], s0[1]);
            ph[1] = pack_bf16(s0[2], s0[3]);
            ph[2] = pack_bf16(s1[0], s1[1]);
            ph[3] = pack_bf16(s1[2], s1[3]);
            pl[0] = pack_bf16(s0[0] - lo_of(ph[0]), s0[1] - hi_of(ph[0]));
            pl[1] = pack_bf16(s0[2] - lo_of(ph[1]), s0[3] - hi_of(ph[1]));
            pl[2] = pack_bf16(s1[0] - lo_of(ph[2]), s1[1] - hi_of(ph[2]));
            pl[3] = pack_bf16(s1[2] - lo_of(ph[3]), s1[3] - hi_of(ph[3]));

            uint32_t vbase = (uint32_t)(ktv * 16 * FA_STRIDE) + vrow_b;
#pragma unroll
            for (int nt = 0; nt < 16; nt++) {
                uint32_t vhf[2], vlf[2];
                uint32_t vaddr = vbase + (uint32_t)(nt * 16);
                ldm_x2t(vhf, sVh + vaddr);
                ldm_x2t(vlf, sVl + vaddr);
                mma_bf16(oc[nt], ph, vhf);
                mma_bf16(oc[nt], ph, vlf);
                mma_bf16(oc[nt], pl, vhf);
            }
        }
    }

    // ---- epilogue ----
    float inv0 = 1.0f / l0, inv1 = 1.0f / l1;
    size_t gr0 = (size_t)(b * T_ + qt * 64 + wid * 16 + (lane >> 2));
    size_t gr1 = gr0 + 8;
#pragma unroll
    for (int nt = 0; nt < 16; nt++) {
        int col = h * 128 + nt * 8 + colb;
        *(float2*)(g_ctx + gr0 * (H_ * D_) + col) = make_float2(oc[nt][0] * inv0, oc[nt][1] * inv0);
        *(float2*)(g_ctx + gr1 * (H_ * D_) + col) = make_float2(oc[nt][2] * inv1, oc[nt][3] * inv1);
    }
}

// ---------------- launch -----------------------------------------------------
extern "C" void kernel_launch(void* const* d_in, const int* in_sizes, int n_in,
                              void* d_out, int out_size)
{
    const float* x  = (const float*)d_in[0];
    const float* wq = (const float*)d_in[2];
    const float* wk = (const float*)d_in[3];
    const float* wv = (const float*)d_in[4];
    const float* wo = (const float*)d_in[5];
    float* out = (float*)d_out;

    float *q, *k, *v, *ctx;
    cudaGetSymbolAddress((void**)&q,   g_q);
    cudaGetSymbolAddress((void**)&k,   g_k);
    cudaGetSymbolAddress((void**)&v,   g_v);
    cudaGetSymbolAddress((void**)&ctx, g_ctx);
    __nv_bfloat16 *xh, *xl, *wqh, *wql, *wkh, *wkl, *wvh, *wvl, *woh, *wol, *ch, *cl;
    __nv_bfloat16 *qhb, *qlb, *khb, *klb, *vhb, *vlb;
    cudaGetSymbolAddress((void**)&xh,  g_xh);   cudaGetSymbolAddress((void**)&xl,  g_xl);
    cudaGetSymbolAddress((void**)&wqh, g_wqh);  cudaGetSymbolAddress((void**)&wql, g_wql);
    cudaGetSymbolAddress((void**)&wkh, g_wkh);  cudaGetSymbolAddress((void**)&wkl, g_wkl);
    cudaGetSymbolAddress((void**)&wvh, g_wvh);  cudaGetSymbolAddress((void**)&wvl, g_wvl);
    cudaGetSymbolAddress((void**)&woh, g_woh);  cudaGetSymbolAddress((void**)&wol, g_wol);
    cudaGetSymbolAddress((void**)&ch,  g_ch);   cudaGetSymbolAddress((void**)&cl,  g_cl);
    cudaGetSymbolAddress((void**)&qhb, g_qhb);  cudaGetSymbolAddress((void**)&qlb, g_qlb);
    cudaGetSymbolAddress((void**)&khb, g_khb);  cudaGetSymbolAddress((void**)&klb, g_klb);
    cudaGetSymbolAddress((void**)&vhb, g_vhb);  cudaGetSymbolAddress((void**)&vlb, g_vlb);

    cudaFuncSetAttribute(gemm_split, cudaFuncAttributeMaxDynamicSharedMemorySize, GEMM_SMEM);
    cudaFuncSetAttribute(flash_mma, cudaFuncAttributeMaxDynamicSharedMemorySize, FA_SMEM);

    // split conversions (inputs)
    conv_split<<<(ROWS * E_ / 2 + 255) / 256, 256>>>(x, xh, xl, ROWS * E_ / 2);
    convT_split<<<dim3((H_ * D_) / 32, E_ / 32), dim3(32, 8)>>>(wq, wqh, wql, E_, H_ * D_);
    convT_split<<<dim3((KVH_ * D_) / 32, E_ / 32), dim3(32, 8)>>>(wk, wkh, wkl, E_, KVH_ * D_);
    convT_split<<<dim3((KVH_ * D_) / 32, E_ / 32), dim3(32, 8)>>>(wv, wvh, wvl, E_, KVH_ * D_);
    convT_split<<<dim3(E_ / 32, (H_ * D_) / 32), dim3(32, 8)>>>(wo, woh, wol, H_ * D_, E_);

    // QKV projections (HMMA)
    gemm_split<<<dim3((H_ * D_) / 128, ROWS / 128), 256, GEMM_SMEM>>>(xh, xl, wqh, wql, q, ROWS, H_ * D_, E_);
    gemm_split<<<dim3((KVH_ * D_) / 128, ROWS / 128), 256, GEMM_SMEM>>>(xh, xl, wkh, wkl, k, ROWS, KVH_ * D_, E_);
    gemm_split<<<dim3((KVH_ * D_) / 128, ROWS / 128), 256, GEMM_SMEM>>>(xh, xl, wvh, wvl, v, ROWS, KVH_ * D_, E_);

    // RoPE (fp32, in place)
    rope_init_kernel<<<1, 64>>>();
    rope_table_kernel<<<T_, 64>>>();
    rope_apply_kernel<<<(ROWS * H_ * 64) / 256, 256>>>(q, H_);
    rope_apply_kernel<<<(ROWS * KVH_ * 64) / 256, 256>>>(k, KVH_);

    // split Q/K/V for tensor-core attention
    conv_split<<<(ROWS * H_ * D_ / 2 + 255) / 256, 256>>>(q, qhb, qlb, ROWS * H_ * D_ / 2);
    conv_split<<<(ROWS * KVH_ * D_ / 2 + 255) / 256, 256>>>(k, khb, klb, ROWS * KVH_ * D_ / 2);
    conv_split<<<(ROWS * KVH_ * D_ / 2 + 255) / 256, 256>>>(v, vhb, vlb, ROWS * KVH_ * D_ / 2);

    // Flash attention (HMMA)
    flash_mma<<<dim3(T_ / 64, B_ * H_), 128, FA_SMEM>>>(qhb, qlb, khb, klb, vhb, vlb);

    // Output projection (HMMA)
    conv_split<<<(ROWS * (H_ * D_) / 2 + 255) / 256, 256>>>(ctx, ch, cl, ROWS * (H_ * D_) / 2);
    gemm_split<<<dim3(E_ / 128, ROWS / 128), 256, GEMM_SMEM>>>(ch, cl, woh, wol, out, ROWS, E_, H_ * D_);

    (void)in_sizes; (void)n_in; (void)out_size;
}